// round 7
// baseline (speedup 1.0000x reference)
#include <cuda_runtime.h>
#include <cuda_bf16.h>

// Problem shape (fixed by the dataset): N=50000, E=800000, Fn=128, Fe=64, D=64
#define MAXN 50176
#define MAXE 800000
#define DD   64
#define FN   128
#define FE   64
#define SLOPE 0.05f

// ---------------- scratch (device globals; no allocation) ----------------
__device__ float4 d_h4[MAXN * 16];     // h [N,64]
__device__ float4 d_accn4[MAXN * 16];  // node-branch accumulator  sum ex * h[j]
__device__ float4 d_te4[MAXN * 16];    // edge-branch accumulator  sum ex * edge_attr[k]
__device__ float  d_hi[MAXN], d_hj[MAXN], d_he[MAXN];
__device__ float  d_sn[MAXN], d_se[MAXN];
__device__ int    d_cntn[MAXN], d_cnte[MAXN];
__device__ float4 d_u4[16];            // u[64] = W_edge^T @ a_edge[D:]
__device__ int    d_ei32[2 * MAXE];    // converted edge indices (int32)
__device__ int    d_not64;             // 1 if int64 interpretation is INVALID

__device__ __forceinline__ float leaky(float v) {
    return v >= 0.f ? v : SLOPE * v;
}

// ---------------- K0: zero accumulators (graph replays need clean state) ----
__global__ void k_zero(int N) {
    int i = blockIdx.x * blockDim.x + threadIdx.x;
    if (i < N * 16) {
        d_accn4[i] = make_float4(0.f, 0.f, 0.f, 0.f);
        d_te4[i]   = make_float4(0.f, 0.f, 0.f, 0.f);
    }
    if (i < N) {
        d_sn[i] = 0.f; d_se[i] = 0.f;
        d_cntn[i] = 0; d_cnte[i] = 0;
    }
    if (i == 0) d_not64 = 0;
}

// ---------------- K0b/K0c: edge-index dtype detection + conversion ---------
// The buffer is either int64[2E] or int32[2E]. If int64-interpretation of any
// entry falls outside [0,N), the data must be int32.
__global__ void k_detect(const void* __restrict__ ei, int twoE, int N) {
    int i = blockIdx.x * blockDim.x + threadIdx.x;
    if (i >= twoE) return;
    long long v = ((const long long*)ei)[i < twoE ? i : 0];
    // guard: only first twoE int64 slots are safely readable if data really is
    // int64; if data is int32 the buffer holds twoE*4 bytes, so only read the
    // first twoE/2 int64 words to stay in bounds.
    if (i >= twoE / 2) return;
    v = ((const long long*)ei)[i];
    if (v < 0 || v >= N) atomicExch(&d_not64, 1);
}

__global__ void k_convert(const void* __restrict__ ei, int twoE) {
    int i = blockIdx.x * blockDim.x + threadIdx.x;
    if (i >= twoE) return;
    int v;
    if (d_not64) v = ((const int*)ei)[i];
    else         v = (int)((const long long*)ei)[i];
    d_ei32[i] = v;
}

// ---------------- K1: h = x @ W_node^T, plus hi/hj/he dot products ----------
__global__ void k_h(const float* __restrict__ x, const float* __restrict__ Wn,
                    const float* __restrict__ a_node, const float* __restrict__ a_edge,
                    int N) {
    __shared__ float Wsh[DD * 129];     // 64 rows x 128, padded stride 129
    __shared__ float xs[8][FN];
    __shared__ float hsh[8][DD];
    int t = threadIdx.x;
    for (int idx = t; idx < DD * FN; idx += 256) {
        int r = idx >> 7, c = idx & 127;
        Wsh[r * 129 + c] = Wn[idx];
    }
    int nb = blockIdx.x * 8;
    for (int idx = t; idx < 8 * FN; idx += 256) {
        int r = idx >> 7, c = idx & 127;
        int n = nb + r;
        xs[r][c] = (n < N) ? x[(long)n * FN + c] : 0.f;
    }
    __syncthreads();

    int d = t & 63, g = t >> 6;   // g in 0..3; each group handles 2 nodes
    for (int s = 0; s < 2; s++) {
        int nl = g * 2 + s;
        const float* wrow = &Wsh[d * 129];
        const float* xrow = xs[nl];
        float acc = 0.f;
        #pragma unroll 16
        for (int f = 0; f < FN; f++) acc = fmaf(xrow[f], wrow[f], acc);
        int n = nb + nl;
        if (n < N) ((float*)d_h4)[(long)n * DD + d] = acc;
        hsh[nl][d] = acc;
    }
    __syncthreads();

    int warp = t >> 5, lane = t & 31;
    int n = nb + warp;
    float v0 = hsh[warp][lane], v1 = hsh[warp][lane + 32];
    float p1 = v0 * a_node[lane]      + v1 * a_node[lane + 32];
    float p2 = v0 * a_node[64 + lane] + v1 * a_node[96 + lane];
    float p3 = v0 * a_edge[lane]      + v1 * a_edge[lane + 32];
    #pragma unroll
    for (int off = 16; off; off >>= 1) {
        p1 += __shfl_xor_sync(0xffffffffu, p1, off);
        p2 += __shfl_xor_sync(0xffffffffu, p2, off);
        p3 += __shfl_xor_sync(0xffffffffu, p3, off);
    }
    if (lane == 0 && n < N) { d_hi[n] = p1; d_hj[n] = p2; d_he[n] = p3; }
}

// ---------------- K1b: u[f] = sum_d a_edge[D+d] * W_edge[d][f] --------------
__global__ void k_u(const float* __restrict__ We, const float* __restrict__ a_edge) {
    int f = threadIdx.x;  // 64 threads
    float acc = 0.f;
    #pragma unroll 8
    for (int dd = 0; dd < DD; dd++) acc = fmaf(a_edge[DD + dd], We[dd * FE + f], acc);
    ((float*)d_u4)[f] = acc;
}

// ---------------- K2: node->node branch, one pass over edges ---------------
// 16 lanes per edge: coalesced 256B gather of h[j], 16 float4 atomic REDs.
__global__ void k_node_edges(int E) {
    int tid = blockIdx.x * blockDim.x + threadIdx.x;
    int k = tid >> 4;
    int l = tid & 15;
    if (k >= E) return;
    int i = d_ei32[k];
    int j = d_ei32[E + k];
    float ex = __expf(leaky(d_hi[i] + d_hj[j]));
    if (l == 0) {
        atomicAdd(&d_sn[i], ex);
        atomicAdd(&d_cntn[i], 1);
    }
    float4 hv = d_h4[(long)j * 16 + l];
    atomicAdd(&d_accn4[(long)i * 16 + l],
              make_float4(ex * hv.x, ex * hv.y, ex * hv.z, ex * hv.w));
}

// ---------------- K3: edge->node branch, one pass over edges ---------------
// Accumulate ex * edge_attr (raw Fe=64 features) into both endpoints; the
// W_edge^T projection is deferred to the per-node finalize (linear => commutes).
__global__ void k_edge_edges(const float* __restrict__ ea, int E) {
    int tid = blockIdx.x * blockDim.x + threadIdx.x;
    int k = tid >> 4;
    int l = tid & 15;
    bool valid = (k < E);
    int kk = valid ? k : 0;

    const float4* ea4 = (const float4*)ea;
    float4 v = ea4[(long)kk * 16 + l];
    float4 u = d_u4[l];
    float p = v.x * u.x + v.y * u.y + v.z * u.z + v.w * u.w;
    #pragma unroll
    for (int off = 8; off; off >>= 1)
        p += __shfl_xor_sync(0xffffffffu, p, off, 16);   // ge = edge_attr[k] . u

    if (!valid) return;
    int i = d_ei32[kk];
    int j = d_ei32[E + kk];
    float exi = __expf(leaky(d_he[i] + p));
    float exj = __expf(leaky(d_he[j] + p));
    if (l == 0) { atomicAdd(&d_se[i], exi); atomicAdd(&d_cnte[i], 1); }
    if (l == 1) { atomicAdd(&d_se[j], exj); atomicAdd(&d_cnte[j], 1); }
    atomicAdd(&d_te4[(long)i * 16 + l],
              make_float4(exi * v.x, exi * v.y, exi * v.z, exi * v.w));
    atomicAdd(&d_te4[(long)j * 16 + l],
              make_float4(exj * v.x, exj * v.y, exj * v.z, exj * v.w));
}

// ---------------- K4: finalize per node ------------------------------------
__global__ void k_final(const float* __restrict__ We, float* __restrict__ out, int N) {
    __shared__ float Wsh[DD * 65];    // W_edge padded
    __shared__ float tsh[4][FE];
    int t = threadIdx.x;  // 256
    for (int idx = t; idx < DD * FE; idx += 256)
        Wsh[(idx >> 6) * 65 + (idx & 63)] = We[idx];
    int nb = blockIdx.x * 4;
    for (int idx = t; idx < 4 * FE; idx += 256) {
        int r = idx >> 6, c = idx & 63;
        int n = nb + r;
        tsh[r][c] = (n < N) ? ((const float*)d_te4)[(long)n * FE + c] : 0.f;
    }
    __syncthreads();

    int d = t & 63, g = t >> 6;
    int n = nb + g;
    if (n >= N) return;

    // ---- node branch (+ self loop folded in analytically) ----
    float exs = __expf(leaky(d_hi[n] + d_hj[n]));
    float s   = d_sn[n] + exs;
    float c   = (float)(d_cntn[n] + 1);
    float hv  = ((const float*)d_h4)[(long)n * DD + d];
    float acc = ((const float*)d_accn4)[(long)n * DD + d];
    float val = (acc + exs * hv) / (s * c);
    out[(long)n * 128 + d] = leaky(val);

    // ---- edge branch: (sum ex * edge_attr) @ W_edge^T ----
    int ce = d_cnte[n];
    float val2 = 0.f;
    if (ce > 0) {
        const float* trow = tsh[g];
        const float* wrow = &Wsh[d * 65];
        float dot = 0.f;
        #pragma unroll 16
        for (int f = 0; f < FE; f++) dot = fmaf(trow[f], wrow[f], dot);
        val2 = dot / (d_se[n] * (float)ce);
    }
    out[(long)n * 128 + 64 + d] = leaky(val2);
}

// ---------------- launch ----------------------------------------------------
extern "C" void kernel_launch(void* const* d_in, const int* in_sizes, int n_in,
                              void* d_out, int out_size) {
    const float* x  = (const float*)d_in[0];
    const float* ea = (const float*)d_in[1];
    const void*  ei = d_in[2];
    const float* Wn = (const float*)d_in[3];
    const float* We = (const float*)d_in[4];
    const float* an = (const float*)d_in[5];
    const float* ae = (const float*)d_in[6];
    float* out = (float*)d_out;

    int N = in_sizes[0] / FN;    // 50000
    int E = in_sizes[1] / FE;    // 800000
    int twoE = 2 * E;

    k_zero<<<(N * 16 + 255) / 256, 256>>>(N);
    k_detect<<<(twoE + 255) / 256, 256>>>(ei, twoE, N);
    k_convert<<<(twoE + 255) / 256, 256>>>(ei, twoE);

    k_h<<<(N + 7) / 8, 256>>>(x, Wn, an, ae, N);
    k_u<<<1, 64>>>(We, ae);

    long long thrE = (long long)E * 16;
    int blocksE = (int)((thrE + 255) / 256);
    k_node_edges<<<blocksE, 256>>>(E);
    k_edge_edges<<<blocksE, 256>>>(ea, E);

    k_final<<<(N + 3) / 4, 256>>>(We, out, N);
}